// round 1
// baseline (speedup 1.0000x reference)
#include <cuda_runtime.h>
#include <cuda_bf16.h>

// Problem: 3D ROI pooling.
//   img:  (1, 256, 256, 256, 8) fp32, layout ((ix*256+iy)*256+iz)*8 + c
//   rois: (1, 64, 6) int32  [x, y, z, w, h, d]
//   out:  (1, 64, 7, 7, 7, 8) fp32
// Per ROI, per pooled axis p in [0,7): src = p * (size/7); i0 = floor(src);
// frac = src - i0; i0c = min(i0, size-1); i1 = min(i0+1, size-1);
// trilinear blend of the 8 corners.
//
// Each cell (roi, px, py, pz) handled by 2 threads, each loading float4
// (4 channels) per corner -> 8 independent LDG.128 per thread (MLP=8).

#define NUM_ROIS 64
#define PS 7
#define CELLS (PS * PS * PS)            // 343
#define DIM 256
#define C 8

__global__ void roi_pool3d_kernel(const float* __restrict__ img,
                                  const int* __restrict__ rois,
                                  float* __restrict__ out)
{
    int tid = blockIdx.x * blockDim.x + threadIdx.x;
    const int total = NUM_ROIS * CELLS * 2;   // 43904
    if (tid >= total) return;

    int half = tid & 1;          // which float4 of the 8-channel vector
    int cell = tid >> 1;
    int roi  = cell / CELLS;
    int rem  = cell - roi * CELLS;
    int px   = rem / (PS * PS);
    int r2   = rem - px * (PS * PS);
    int py   = r2 / PS;
    int pz   = r2 - py * PS;

    const int* r = rois + roi * 6;
    int x = r[0], y = r[1], z = r[2];
    int w = r[3], h = r[4], d = r[5];

    // --- axis coords (match reference arithmetic exactly in fp32) ---
    float sx = (float)px * ((float)w / (float)PS);
    int ix0 = (int)floorf(sx);
    float fx = sx - (float)ix0;
    int ix1 = min(ix0 + 1, w - 1);
    ix0 = min(ix0, w - 1);
    ix0 += x; ix1 += x;

    float sy = (float)py * ((float)h / (float)PS);
    int iy0 = (int)floorf(sy);
    float fy = sy - (float)iy0;
    int iy1 = min(iy0 + 1, h - 1);
    iy0 = min(iy0, h - 1);
    iy0 += y; iy1 += y;

    float sz = (float)pz * ((float)d / (float)PS);
    int iz0 = (int)floorf(sz);
    float fz = sz - (float)iz0;
    int iz1 = min(iz0 + 1, d - 1);
    iz0 = min(iz0, d - 1);
    iz0 += z; iz1 += z;

    // float4 index: ((ix*256+iy)*256+iz)*8 floats / 4 = ((ix*256+iy)*256+iz)*2
    const float4* __restrict__ base = (const float4*)img;
    size_t b000 = ((size_t)((ix0 * DIM + iy0) * DIM + iz0)) * 2 + half;
    size_t b001 = ((size_t)((ix0 * DIM + iy0) * DIM + iz1)) * 2 + half;
    size_t b010 = ((size_t)((ix0 * DIM + iy1) * DIM + iz0)) * 2 + half;
    size_t b011 = ((size_t)((ix0 * DIM + iy1) * DIM + iz1)) * 2 + half;
    size_t b100 = ((size_t)((ix1 * DIM + iy0) * DIM + iz0)) * 2 + half;
    size_t b101 = ((size_t)((ix1 * DIM + iy0) * DIM + iz1)) * 2 + half;
    size_t b110 = ((size_t)((ix1 * DIM + iy1) * DIM + iz0)) * 2 + half;
    size_t b111 = ((size_t)((ix1 * DIM + iy1) * DIM + iz1)) * 2 + half;

    // Issue all 8 loads back-to-back (independent -> MLP = 8)
    float4 v000 = base[b000];
    float4 v001 = base[b001];
    float4 v010 = base[b010];
    float4 v011 = base[b011];
    float4 v100 = base[b100];
    float4 v101 = base[b101];
    float4 v110 = base[b110];
    float4 v111 = base[b111];

    float gz = 1.0f - fz, gy = 1.0f - fy, gx = 1.0f - fx;

    float4 o;
    {
        float c00, c01, c10, c11, c0, c1;
        c00 = v000.x * gz + v001.x * fz;
        c01 = v010.x * gz + v011.x * fz;
        c10 = v100.x * gz + v101.x * fz;
        c11 = v110.x * gz + v111.x * fz;
        c0 = c00 * gy + c01 * fy;
        c1 = c10 * gy + c11 * fy;
        o.x = c0 * gx + c1 * fx;

        c00 = v000.y * gz + v001.y * fz;
        c01 = v010.y * gz + v011.y * fz;
        c10 = v100.y * gz + v101.y * fz;
        c11 = v110.y * gz + v111.y * fz;
        c0 = c00 * gy + c01 * fy;
        c1 = c10 * gy + c11 * fy;
        o.y = c0 * gx + c1 * fx;

        c00 = v000.z * gz + v001.z * fz;
        c01 = v010.z * gz + v011.z * fz;
        c10 = v100.z * gz + v101.z * fz;
        c11 = v110.z * gz + v111.z * fz;
        c0 = c00 * gy + c01 * fy;
        c1 = c10 * gy + c11 * fy;
        o.z = c0 * gx + c1 * fx;

        c00 = v000.w * gz + v001.w * fz;
        c01 = v010.w * gz + v011.w * fz;
        c10 = v100.w * gz + v101.w * fz;
        c11 = v110.w * gz + v111.w * fz;
        c0 = c00 * gy + c01 * fy;
        c1 = c10 * gy + c11 * fy;
        o.w = c0 * gx + c1 * fx;
    }

    ((float4*)out)[(size_t)cell * 2 + half] = o;
}

extern "C" void kernel_launch(void* const* d_in, const int* in_sizes, int n_in,
                              void* d_out, int out_size)
{
    const float* img  = (const float*)d_in[0];
    const int*   rois = (const int*)d_in[1];
    float*       out  = (float*)d_out;

    const int total = NUM_ROIS * CELLS * 2;   // 43904 threads
    const int threads = 256;
    const int blocks = (total + threads - 1) / threads;
    roi_pool3d_kernel<<<blocks, threads>>>(img, rois, out);
}